// round 1
// baseline (speedup 1.0000x reference)
#include <cuda_runtime.h>
#include <math.h>

// Problem constants (fixed shapes from setup_inputs)
#define BB    8
#define NA    5
#define NC    8
#define NH    192
#define NW    192
#define TT    50
#define ATTRS 15            // 7 + NC
#define NHW   (NH*NW)       // 36864
#define CELLS (BB*NA*NHW)   // 1,474,560
#define NT    (BB*TT)       // 400
#define NIGN  (NT*NA)       // 2000
#define THRESH 0.6f

// ---------------- device scratch (static; no allocation) ----------------
__device__ double g_acc[7];   // 0:S_noobj 1:S_objconf 2:Sx 3:Sy 4:Sw 5:Sh 6:Sce
__device__ int    g_nObj;
__device__ int    g_removed;  // cells removed from the noobj set
__device__ int    g_objCell[NT];
__device__ float  g_objTx[NT], g_objTy[NT], g_objTw[NT], g_objTh[NT];
__device__ int    g_objLabel[NT];
__device__ int    g_ign[NIGN];

__device__ __forceinline__ float sigmoidf_(float v) { return 1.0f / (1.0f + expf(-v)); }
__device__ __forceinline__ float clip_p(float p) {
    return fminf(fmaxf(p, 1e-7f), 1.0f - 1e-7f);
}
__device__ __forceinline__ float bce0f(float v) {   // tconf = 0 term
    float p = clip_p(sigmoidf_(v));
    return -log1pf(-p);
}

// ---------------- Kernel A: build targets (1 block) ----------------
__global__ void kA(const float* __restrict__ tg, const float* __restrict__ anchors) {
    __shared__ int s_valid[NT], s_best[NT], s_gi[NT], s_gj[NT];
    int t = threadIdx.x;

    if (t == 0) {
        #pragma unroll
        for (int i = 0; i < 7; i++) g_acc[i] = 0.0;
        g_nObj = 0;
        g_removed = 0;
    }

    int   valid = 0, best = 0, gi = 0, gj = 0, b = 0;
    float gx = 0.f, gy = 0.f, gw = 0.f, gh = 0.f, aw_b = 1.f, ah_b = 1.f;
    float r0 = 0.f;

    if (t < NT) {
        const float* r = tg + (size_t)t * 5;
        r0 = r[0];
        float s5 = r[0] + r[1] + r[2] + r[3] + r[4];
        valid = (s5 != 0.0f);
        gx = r[1] * NW; gy = r[2] * NH; gw = r[3] * NW; gh = r[4] * NH;
        gi = (int)floorf(gx); gj = (int)floorf(gy);
        b = t / TT;

        float bestIou = -1.0f;
        #pragma unroll
        for (int a = 0; a < NA; a++) {
            float aw = anchors[2 * a], ah = anchors[2 * a + 1];
            float inter = fminf(gw, aw) * fminf(gh, ah);
            float uni   = gw * gh + aw * ah - inter;
            float iou   = inter / uni;
            if (iou > bestIou) { bestIou = iou; best = a; aw_b = aw; ah_b = ah; }
            g_ign[t * NA + a] = (valid && iou > THRESH)
                                  ? (((b * NA + a) * NH + gj) * NW + gi) : -1;
        }
        s_valid[t] = valid; s_best[t] = best; s_gi[t] = gi; s_gj[t] = gj;
    }
    __syncthreads();

    if (t < NT && valid) {
        // last-write-wins within a batch: winner iff no later same-cell target
        bool winner = true;
        int tt = t % TT;
        for (int t2 = tt + 1; t2 < TT; t2++) {
            int u = b * TT + t2;
            if (s_valid[u] && s_best[u] == best && s_gi[u] == gi && s_gj[u] == gj) {
                winner = false; break;
            }
        }
        if (winner) {
            int pos = atomicAdd(&g_nObj, 1);
            g_objCell[pos]  = ((b * NA + best) * NH + gj) * NW + gi;
            g_objTx[pos]    = gx - floorf(gx);
            g_objTy[pos]    = gy - floorf(gy);
            g_objTw[pos]    = logf(gw / aw_b + 1e-16f);
            g_objTh[pos]    = logf(gh / ah_b + 1e-16f);
            g_objLabel[pos] = (int)r0;
        }
    }
}

// ---------------- Kernel B: dense bce0 reduction over conf channel ----------------
__global__ void kB(const float* __restrict__ x) {
    int tid = blockIdx.x * blockDim.x + threadIdx.x;   // one thread = 4 cells
    double local = 0.0;
    if (tid < CELLS / 4) {
        int cell4 = tid * 4;
        int i0 = cell4 % NW;
        int j  = (cell4 / NW) % NH;
        int ba = cell4 / NHW;                 // b*NA + a
        size_t off = ((size_t)ba * ATTRS + 6) * NHW + (size_t)j * NW + i0;
        float4 v = *(const float4*)(x + off);
        local = (double)bce0f(v.x) + (double)bce0f(v.y)
              + (double)bce0f(v.z) + (double)bce0f(v.w);
    }
    #pragma unroll
    for (int o = 16; o; o >>= 1) local += __shfl_down_sync(0xffffffffu, local, o);
    if ((threadIdx.x & 31) == 0) atomicAdd(&g_acc[0], local);
}

// ---------------- Kernel C_obj: per-object corrections + coord/cls loss ----------------
__global__ void kCobj(const float* __restrict__ x) {
    int k = blockIdx.x * blockDim.x + threadIdx.x;
    if (k >= g_nObj) return;
    int cell = g_objCell[k];
    int i  = cell % NW;
    int j  = (cell / NW) % NH;
    int ba = cell / NHW;
    size_t base = (size_t)ba * ATTRS * NHW + (size_t)j * NW + i;

    float x0 = x[base + 0 * (size_t)NHW];
    float x1 = x[base + 1 * (size_t)NHW];
    float x2 = x[base + 2 * (size_t)NHW];
    float x3 = x[base + 3 * (size_t)NHW];
    float xc = x[base + 6 * (size_t)NHW];

    float dx = sigmoidf_(x0) - g_objTx[k];
    float dy = sigmoidf_(x1) - g_objTy[k];
    float dw = x2 - g_objTw[k];
    float dh = x3 - g_objTh[k];
    atomicAdd(&g_acc[2], (double)(dx * dx));
    atomicAdd(&g_acc[3], (double)(dy * dy));
    atomicAdd(&g_acc[4], (double)(dw * dw));
    atomicAdd(&g_acc[5], (double)(dh * dh));

    float p = clip_p(sigmoidf_(xc));
    atomicAdd(&g_acc[1], (double)(-logf(p)));      // obj conf bce (tconf=1)
    atomicAdd(&g_acc[0], (double)log1pf(-p));      // subtract bce0 from noobj sum
    atomicAdd(&g_removed, 1);

    // class loss: log_softmax over sigmoid(logits)
    float s[NC];
    float m = -1e30f;
    #pragma unroll
    for (int c = 0; c < NC; c++) {
        s[c] = sigmoidf_(x[base + (size_t)(7 + c) * NHW]);
        m = fmaxf(m, s[c]);
    }
    float sum = 0.f;
    #pragma unroll
    for (int c = 0; c < NC; c++) sum += expf(s[c] - m);
    float lse = m + logf(sum);
    float ce  = lse - s[g_objLabel[k]];
    atomicAdd(&g_acc[6], (double)ce);
}

// ---------------- Kernel C_ign: ignore-cell corrections (dedup, excl. obj cells) ----------------
__global__ void kCign(const float* __restrict__ x) {
    int k = blockIdx.x * blockDim.x + threadIdx.x;
    if (k >= NIGN) return;
    int cell = g_ign[k];
    if (cell < 0) return;
    int n = g_nObj;
    for (int q = 0; q < n; q++) if (g_objCell[q] == cell) return;   // best beats ignore
    for (int q = 0; q < k; q++) if (g_ign[q] == cell) return;       // dedup (first wins)
    int i  = cell % NW;
    int j  = (cell / NW) % NH;
    int ba = cell / NHW;
    float xc = x[((size_t)ba * ATTRS + 6) * NHW + (size_t)j * NW + i];
    atomicAdd(&g_acc[0], -(double)bce0f(xc));
    atomicAdd(&g_removed, 1);
}

// ---------------- Kernel D: finalize ----------------
__global__ void kD(float* __restrict__ out) {
    double nobj = (double)g_nObj;
    double cnt  = (double)CELLS - (double)g_removed;
    double loss = (g_acc[2] + g_acc[3] + g_acc[4] + g_acc[5]
                   + g_acc[1] + g_acc[6] / (double)BB) / nobj
                + g_acc[0] / cnt;
    out[0] = (float)loss;
}

// ---------------- launch ----------------
extern "C" void kernel_launch(void* const* d_in, const int* in_sizes, int n_in,
                              void* d_out, int out_size) {
    const float* x  = (const float*)d_in[0];
    const float* tg = (const float*)d_in[1];
    const float* an = (const float*)d_in[2];
    float* out = (float*)d_out;

    kA<<<1, 512>>>(tg, an);
    kB<<<(CELLS / 4 + 255) / 256, 256>>>(x);
    kCobj<<<2, 256>>>(x);
    kCign<<<(NIGN + 255) / 256, 256>>>(x);
    kD<<<1, 1>>>(out);
}